// round 5
// baseline (speedup 1.0000x reference)
#include <cuda_runtime.h>
#include <cuda_bf16.h>
#include <math.h>

// Problem constants
#define BATCH 2
#define SEQ   4096
#define DMODEL 768
#define NHEAD 12
#define DHEAD 64
#define NLAYER 2
#define WIN   256
#define DFF   3072
#define MROWS (BATCH * SEQ)   // 8192

// ---------------- scratch (static device allocations; no cudaMalloc) ----------------
__device__ float g_x [MROWS * DMODEL];
__device__ float g_q [MROWS * DMODEL];
__device__ float g_k [MROWS * DMODEL];
__device__ float g_v [MROWS * DMODEL];
__device__ float g_a [MROWS * DMODEL];
__device__ float g_ff[MROWS * DFF];

// ---------------- helpers ----------------
__device__ __forceinline__ float gelu_tanh(float x) {
    float c = x + 0.044715f * x * x * x;
    return 0.5f * x * (1.0f + tanhf(0.7978845608028654f * c));
}

__device__ __forceinline__ unsigned f2tf32(float x) {
    unsigned r;
    asm("cvt.rna.tf32.f32 %0, %1;" : "=r"(r) : "f"(x));
    return r;
}

// block-wide sum of two values (blockDim.x == 256)
__device__ __forceinline__ void block_sum2(float& s1, float& s2) {
    #pragma unroll
    for (int o = 16; o; o >>= 1) {
        s1 += __shfl_xor_sync(0xffffffffu, s1, o);
        s2 += __shfl_xor_sync(0xffffffffu, s2, o);
    }
    __shared__ float sh1[8], sh2[8];
    int lane = threadIdx.x & 31, w = threadIdx.x >> 5;
    if (lane == 0) { sh1[w] = s1; sh2[w] = s2; }
    __syncthreads();
    float t1 = 0.f, t2 = 0.f;
    #pragma unroll
    for (int i = 0; i < 8; i++) { t1 += sh1[i]; t2 += sh2[i]; }
    s1 = t1; s2 = t2;
}

// ---------------- embedding + layernorm ----------------
__global__ void embed_ln_kernel(const int* __restrict__ ids,
                                const float* __restrict__ wemb,
                                const float* __restrict__ pemb,
                                const float* __restrict__ g,
                                const float* __restrict__ bt,
                                float* __restrict__ x) {
    int token = blockIdx.x;            // b*SEQ + s
    int s = token % SEQ;
    int id = ids[token];
    const float* wp = wemb + (size_t)id * DMODEL;
    const float* pp = pemb + (size_t)s * DMODEL;
    float* xp = x + (size_t)token * DMODEL;

    float v[3], s1 = 0.f, s2 = 0.f;
    #pragma unroll
    for (int j = 0; j < 3; j++) {
        int d = threadIdx.x + 256 * j;
        float val = wp[d] + pp[d];
        v[j] = val; s1 += val; s2 += val * val;
    }
    block_sum2(s1, s2);
    float mean = s1 * (1.0f / DMODEL);
    float var  = s2 * (1.0f / DMODEL) - mean * mean;
    float rstd = rsqrtf(var + 1e-5f);
    #pragma unroll
    for (int j = 0; j < 3; j++) {
        int d = threadIdx.x + 256 * j;
        xp[d] = (v[j] - mean) * rstd * g[d] + bt[d];
    }
}

// ---------------- x = LN(x + r) * g + b  (in place) ----------------
__global__ void addln_kernel(float* __restrict__ x,
                             const float* __restrict__ r,
                             const float* __restrict__ g,
                             const float* __restrict__ bt) {
    int token = blockIdx.x;
    float* xp = x + (size_t)token * DMODEL;
    const float* rp = r + (size_t)token * DMODEL;

    float v[3], s1 = 0.f, s2 = 0.f;
    #pragma unroll
    for (int j = 0; j < 3; j++) {
        int d = threadIdx.x + 256 * j;
        float val = xp[d] + rp[d];
        v[j] = val; s1 += val; s2 += val * val;
    }
    block_sum2(s1, s2);
    float mean = s1 * (1.0f / DMODEL);
    float var  = s2 * (1.0f / DMODEL) - mean * mean;
    float rstd = rsqrtf(var + 1e-5f);
    #pragma unroll
    for (int j = 0; j < 3; j++) {
        int d = threadIdx.x + 256 * j;
        xp[d] = (v[j] - mean) * rstd * g[d] + bt[d];
    }
}

// ---------------- tf32 tensor-core GEMM: C[M,N] = act(A[M,K] @ W[K,N] + bias) ----------------
// Block tile 128x128, BK=32, 256 threads = 8 warps in 4(m) x 2(n) grid,
// warp tile 32x64 = 2(m16) x 8(n8) mma fragments, mma.sync.m16n8k8.tf32.
// Smem staged k-major with stride 136 words (136 % 32 == 8 -> fragment
// reads hit banks 8*tg+gid, all distinct -> conflict-free).
// Register double-buffering: next tile's global loads issue before compute,
// get stored to smem after compute -> LDG latency hidden behind MMA work.
// Requires M%128==0, N%128==0, K%32==0 (true for all shapes used).
template <int ACT>
__global__ void __launch_bounds__(256)
gemm_kernel(const float* __restrict__ A, const float* __restrict__ W,
            const float* __restrict__ bias, float* __restrict__ C,
            int M, int N, int K) {
    __shared__ unsigned As[32][136];   // [k][m] tf32 bits
    __shared__ unsigned Bs[32][136];   // [k][n] tf32 bits

    const int tid = threadIdx.x;
    const int lane = tid & 31;
    const int wid = tid >> 5;
    const int gid = lane >> 2;        // 0..7  (group id)
    const int tg  = lane & 3;         // 0..3  (thread-in-group)
    const int warp_m = wid & 3;       // 0..3
    const int warp_n = wid >> 2;      // 0..1
    const int n0 = blockIdx.x * 128;
    const int m0 = blockIdx.y * 128;

    // A global-load mapping: row = tid>>1 (0..127), kc = (tid&1)*16
    const int a_row = tid >> 1;
    const int a_kc  = (tid & 1) * 16;
    // B global-load mapping: krow = tid>>3 (0..31), nc = (tid&7)*16
    const int b_kr  = tid >> 3;
    const int b_nc  = (tid & 7) * 16;

    const float* Ag = A + (size_t)(m0 + a_row) * K + a_kc;
    const float* Wg = W + (size_t)b_kr * N + n0 + b_nc;

    float4 a_reg[4], b_reg[4];

    float acc[2][8][4];
    #pragma unroll
    for (int i = 0; i < 2; i++)
        #pragma unroll
        for (int j = 0; j < 8; j++)
            #pragma unroll
            for (int e = 0; e < 4; e++) acc[i][j][e] = 0.f;

    // prologue: load + stage tile 0
    #pragma unroll
    for (int j = 0; j < 4; j++) {
        a_reg[j] = *(const float4*)(Ag + 4 * j);
        b_reg[j] = *(const float4*)(Wg + 4 * j);
    }
    #pragma unroll
    for (int j = 0; j < 4; j++) {
        As[a_kc + 4 * j + 0][a_row] = f2tf32(a_reg[j].x);
        As[a_kc + 4 * j + 1][a_row] = f2tf32(a_reg[j].y);
        As[a_kc + 4 * j + 2][a_row] = f2tf32(a_reg[j].z);
        As[a_kc + 4 * j + 3][a_row] = f2tf32(a_reg[j].w);
        uint4 u;
        u.x = f2tf32(b_reg[j].x); u.y = f2tf32(b_reg[j].y);
        u.z = f2tf32(b_reg[j].z); u.w = f2tf32(b_reg[j].w);
        *(uint4*)(&Bs[b_kr][b_nc + 4 * j]) = u;
    }
    __syncthreads();

    for (int kt = 0; kt < K; kt += 32) {
        const bool has_next = (kt + 32) < K;
        // issue next tile's global loads early; latency overlaps the MMAs below
        if (has_next) {
            #pragma unroll
            for (int j = 0; j < 4; j++) {
                a_reg[j] = *(const float4*)(Ag + kt + 32 + 4 * j);
                b_reg[j] = *(const float4*)(Wg + (size_t)(kt + 32) * N + 4 * j);
            }
        }

        #pragma unroll
        for (int kk = 0; kk < 4; kk++) {
            const int k8 = kk * 8;
            unsigned af[2][4], bf[8][2];
            #pragma unroll
            for (int fm = 0; fm < 2; fm++) {
                int mb = warp_m * 32 + fm * 16;
                af[fm][0] = As[k8 + tg    ][mb + gid];
                af[fm][1] = As[k8 + tg    ][mb + gid + 8];
                af[fm][2] = As[k8 + tg + 4][mb + gid];
                af[fm][3] = As[k8 + tg + 4][mb + gid + 8];
            }
            #pragma unroll
            for (int fn = 0; fn < 8; fn++) {
                int nb = warp_n * 64 + fn * 8;
                bf[fn][0] = Bs[k8 + tg    ][nb + gid];
                bf[fn][1] = Bs[k8 + tg + 4][nb + gid];
            }
            #pragma unroll
            for (int fm = 0; fm < 2; fm++)
                #pragma unroll
                for (int fn = 0; fn < 8; fn++) {
                    asm volatile(
                        "mma.sync.aligned.m16n8k8.row.col.f32.tf32.tf32.f32 "
                        "{%0,%1,%2,%3}, {%4,%5,%6,%7}, {%8,%9}, {%0,%1,%2,%3};"
                        : "+f"(acc[fm][fn][0]), "+f"(acc[fm][fn][1]),
                          "+f"(acc[fm][fn][2]), "+f"(acc[fm][fn][3])
                        : "r"(af[fm][0]), "r"(af[fm][1]), "r"(af[fm][2]), "r"(af[fm][3]),
                          "r"(bf[fn][0]), "r"(bf[fn][1]));
                }
        }

        if (has_next) {
            __syncthreads();   // everyone done reading current tile
            #pragma unroll
            for (int j = 0; j < 4; j++) {
                As[a_kc + 4 * j + 0][a_row] = f2tf32(a_reg[j].x);
                As[a_kc + 4 * j + 1][a_row] = f2tf32(a_reg[j].y);
                As[a_kc + 4 * j + 2][a_row] = f2tf32(a_reg[j].z);
                As[a_kc + 4 * j + 3][a_row] = f2tf32(a_reg[j].w);
                uint4 u;
                u.x = f2tf32(b_reg[j].x); u.y = f2tf32(b_reg[j].y);
                u.z = f2tf32(b_reg[j].z); u.w = f2tf32(b_reg[j].w);
                *(uint4*)(&Bs[b_kr][b_nc + 4 * j]) = u;
            }
            __syncthreads();   // tile staged for next iteration
        }
    }

    // epilogue: c0 at (gid, 2tg), c1 (gid, 2tg+1), c2 (gid+8, 2tg), c3 (gid+8, 2tg+1)
    #pragma unroll
    for (int fn = 0; fn < 8; fn++) {
        int nb = n0 + warp_n * 64 + fn * 8 + 2 * tg;
        float b0 = bias[nb], b1 = bias[nb + 1];
        #pragma unroll
        for (int fm = 0; fm < 2; fm++) {
            int mb = m0 + warp_m * 32 + fm * 16;
            float v0 = acc[fm][fn][0] + b0;
            float v1 = acc[fm][fn][1] + b1;
            float v2 = acc[fm][fn][2] + b0;
            float v3 = acc[fm][fn][3] + b1;
            if (ACT == 1) {
                v0 = gelu_tanh(v0); v1 = gelu_tanh(v1);
                v2 = gelu_tanh(v2); v3 = gelu_tanh(v3);
            }
            *(float2*)(C + (size_t)(mb + gid)     * N + nb) = make_float2(v0, v1);
            *(float2*)(C + (size_t)(mb + gid + 8) * N + nb) = make_float2(v2, v3);
        }
    }
}

// ---------------- sliding-window + global attention (queries t >= 1) ----------------
// One warp per (b, h, t) query. q/k/v/out layout: (B, S, H, DH) == (MROWS, 768).
// lane l owns dims 2l, 2l+1. Branchless masking: masked keys get score -1e30
// so their softmax weight underflows to exactly 0 (matches reference -1e9 fill).
__global__ void attn_kernel(const float* __restrict__ q,
                            const float* __restrict__ k,
                            const float* __restrict__ v,
                            const int* __restrict__ att,
                            float* __restrict__ out) {
    int warp = (blockIdx.x * blockDim.x + threadIdx.x) >> 5;
    int lane = threadIdx.x & 31;
    int t = warp % SEQ;
    int h = (warp / SEQ) % NHEAD;
    int b = warp / (SEQ * NHEAD);
    if (t == 0) return;   // handled by global_attn_kernel

    const float scale = 0.125f;  // DHEAD^-0.5
    const float2* qp = (const float2*)(q + ((size_t)(b * SEQ + t) * NHEAD + h) * DHEAD);
    float2 qv = qp[lane];
    float q0 = qv.x * scale, q1 = qv.y * scale;

    const float* kb = k + ((size_t)(b * SEQ) * NHEAD + h) * DHEAD;
    const float* vb = v + ((size_t)(b * SEQ) * NHEAD + h) * DHEAD;
    const int* ab = att + b * SEQ;
    const int STR = NHEAD * DHEAD;   // 768

    float m = -1e30f, l = 0.f, a0 = 0.f, a1 = 0.f;

    auto score_of = [&](int s) -> float {
        float2 kk = ((const float2*)(kb + (size_t)s * STR))[lane];
        float part = q0 * kk.x + q1 * kk.y;
        #pragma unroll
        for (int o = 16; o; o >>= 1) part += __shfl_xor_sync(0xffffffffu, part, o);
        return part;
    };
    auto update = [&](int s, float sc) {
        float mn = fmaxf(m, sc);
        float corr = __expf(m - mn);
        float p = __expf(sc - mn);
        float2 vv = ((const float2*)(vb + (size_t)s * STR))[lane];
        a0 = a0 * corr + p * vv.x;
        a1 = a1 * corr + p * vv.y;
        l = l * corr + p;
        m = mn;
    };

    update(0, score_of(0));  // global key (index 0), not gated by mask per reference

    int lo = t - WIN; if (lo < 1) lo = 1;
    int hi = t + WIN; if (hi > SEQ - 1) hi = SEQ - 1;

    int s = lo;
    for (; s + 1 <= hi; s += 2) {
        float2 k0 = ((const float2*)(kb + (size_t)s * STR))[lane];
        float2 k1 = ((const float2*)(kb + (size_t)(s + 1) * STR))[lane];
        float p0 = q0 * k0.x + q1 * k0.y;
        float p1 = q0 * k1.x + q1 * k1.y;
        #pragma unroll
        for (int o = 16; o; o >>= 1) {
            p0 += __shfl_xor_sync(0xffffffffu, p0, o);
            p1 += __shfl_xor_sync(0xffffffffu, p1, o);
        }
        float sc0 = p0 + (ab[s]     > 0 ? 0.f : -1e30f);
        float sc1 = p1 + (ab[s + 1] > 0 ? 0.f : -1e30f);
        update(s, sc0);
        update(s + 1, sc1);
    }
    if (s <= hi) {
        float sc = score_of(s) + (ab[s] > 0 ? 0.f : -1e30f);
        update(s, sc);
    }

    float inv = 1.0f / l;
    float2* op = (float2*)(out + ((size_t)(b * SEQ + t) * NHEAD + h) * DHEAD);
    op[lane] = make_float2(a0 * inv, a1 * inv);
}

// ---------------- global query (t == 0): full attention over all masked keys ----------------
__global__ void global_attn_kernel(const float* __restrict__ q,
                                   const float* __restrict__ k,
                                   const float* __restrict__ v,
                                   const int* __restrict__ att,
                                   float* __restrict__ out) {
    int h = blockIdx.x % NHEAD;
    int b = blockIdx.x / NHEAD;
    int lane = threadIdx.x & 31;
    int w = threadIdx.x >> 5;

    const float scale = 0.125f;
    const float2* qp = (const float2*)(q + ((size_t)(b * SEQ) * NHEAD + h) * DHEAD);
    float2 qv = qp[lane];
    float q0 = qv.x * scale, q1 = qv.y * scale;

    const float* kb = k + ((size_t)(b * SEQ) * NHEAD + h) * DHEAD;
    const float* vb = v + ((size_t)(b * SEQ) * NHEAD + h) * DHEAD;
    const int* ab = att + b * SEQ;
    const int STR = NHEAD * DHEAD;

    float m = -1e30f, l = 0.f, a0 = 0.f, a1 = 0.f;

    for (int s = w; s < SEQ; s += 8) {
        float2 kk = ((const float2*)(kb + (size_t)s * STR))[lane];
        float part = q0 * kk.x + q1 * kk.y;
        #pragma unroll
        for (int o = 16; o; o >>= 1) part += __shfl_xor_sync(0xffffffffu, part, o);
        float sc = part + (ab[s] > 0 ? 0.f : -1e30f);
        float mn = fmaxf(m, sc);
        float corr = __expf(m - mn);
        float p = __expf(sc - mn);
        float2 vv = ((const float2*)(vb + (size_t)s * STR))[lane];
        a0 = a0 * corr + p * vv.x;
        a1 = a1 * corr + p * vv.y;
        l = l * corr + p;
        m = mn;
    }

    __shared__ float sm[8], sl[8];
    __shared__ float sacc[8][64];
    if (lane == 0) { sm[w] = m; sl[w] = l; }
    sacc[w][2 * lane]     = a0;
    sacc[w][2 * lane + 1] = a1;
    __syncthreads();

    if (w == 0) {
        float M = -1e30f;
        #pragma unroll
        for (int i = 0; i < 8; i++) M = fmaxf(M, sm[i]);
        float L = 0.f, o0 = 0.f, o1 = 0.f;
        #pragma unroll
        for (int i = 0; i < 8; i++) {
            float c = __expf(sm[i] - M);
            L  += sl[i] * c;
            o0 += sacc[i][2 * lane]     * c;
            o1 += sacc[i][2 * lane + 1] * c;
        }
        float inv = 1.0f / L;
        float2* op = (float2*)(out + ((size_t)(b * SEQ) * NHEAD + h) * DHEAD);
        op[lane] = make_float2(o0 * inv, o1 * inv);
    }
}

// ---------------- pooled head: mean-pool -> relu MLP -> sigmoid*4 ----------------
__global__ void head_kernel(const float* __restrict__ x,
                            const int* __restrict__ att,
                            const float* __restrict__ Wh1, const float* __restrict__ bh1,
                            const float* __restrict__ Wh2, const float* __restrict__ bh2,
                            float* __restrict__ out) {
    int b = blockIdx.x;
    int tid = threadIdx.x;
    __shared__ float pooled[DMODEL];
    __shared__ float h[256];

    float cnt = 0.f, dummy = 0.f;
    for (int s = tid; s < SEQ; s += 256) cnt += (float)att[b * SEQ + s];
    block_sum2(cnt, dummy);
    float denom = fmaxf(cnt, 1e-9f);

    for (int d = tid; d < DMODEL; d += 256) {
        float ssum = 0.f;
        const float* xp = x + (size_t)b * SEQ * DMODEL + d;
        for (int s = 0; s < SEQ; s++)
            ssum += xp[(size_t)s * DMODEL] * (float)att[b * SEQ + s];
        pooled[d] = ssum / denom;
    }
    __syncthreads();

    {
        float acc = bh1[tid];
        for (int kk = 0; kk < DMODEL; kk++)
            acc += pooled[kk] * Wh1[kk * 256 + tid];
        h[tid] = fmaxf(acc, 0.f);
    }
    __syncthreads();

    if (tid < 14) {
        float acc = bh2[tid];
        for (int kk = 0; kk < 256; kk++)
            acc += h[kk] * Wh2[kk * 14 + tid];
        out[b * 14 + tid] = 4.0f / (1.0f + expf(-acc));
    }
}

// ---------------- launch ----------------
extern "C" void kernel_launch(void* const* d_in, const int* in_sizes, int n_in,
                              void* d_out, int out_size) {
    const int*   ids  = (const int*)  d_in[0];
    const int*   att  = (const int*)  d_in[1];
    const float* wemb = (const float*)d_in[2];
    const float* pemb = (const float*)d_in[3];
    const float* eg   = (const float*)d_in[4];
    const float* eb   = (const float*)d_in[5];
    const float* Wq   = (const float*)d_in[6];
    const float* bq   = (const float*)d_in[7];
    const float* Wk   = (const float*)d_in[8];
    const float* bk   = (const float*)d_in[9];
    const float* Wv   = (const float*)d_in[10];
    const float* bv   = (const float*)d_in[11];
    const float* Wo   = (const float*)d_in[12];
    const float* bo   = (const float*)d_in[13];
    const float* ln1g = (const float*)d_in[14];
    const float* ln1b = (const float*)d_in[15];
    const float* Wf1  = (const float*)d_in[16];
    const float* bf1  = (const float*)d_in[17];
    const float* Wf2  = (const float*)d_in[18];
    const float* bf2  = (const float*)d_in[19];
    const float* ln2g = (const float*)d_in[20];
    const float* ln2b = (const float*)d_in[21];
    const float* Wh1  = (const float*)d_in[22];
    const float* bh1  = (const float*)d_in[23];
    const float* Wh2  = (const float*)d_in[24];
    const float* bh2  = (const float*)d_in[25];

    float *x, *q, *k, *v, *a, *ff;
    cudaGetSymbolAddress((void**)&x,  g_x);
    cudaGetSymbolAddress((void**)&q,  g_q);
    cudaGetSymbolAddress((void**)&k,  g_k);
    cudaGetSymbolAddress((void**)&v,  g_v);
    cudaGetSymbolAddress((void**)&a,  g_a);
    cudaGetSymbolAddress((void**)&ff, g_ff);

    dim3 gD(DMODEL / 128, MROWS / 128);   // (6, 64)
    dim3 gF(DFF / 128,    MROWS / 128);   // (24, 64)

    embed_ln_kernel<<<MROWS, 256>>>(ids, wemb, pemb, eg, eb, x);

    for (int l = 0; l < NLAYER; l++) {
        const size_t wD = (size_t)l * DMODEL * DMODEL;
        gemm_kernel<0><<<gD, 256>>>(x, Wq + wD, bq + l * DMODEL, q, MROWS, DMODEL, DMODEL);
        gemm_kernel<0><<<gD, 256>>>(x, Wk + wD, bk + l * DMODEL, k, MROWS, DMODEL, DMODEL);
        gemm_kernel<0><<<gD, 256>>>(x, Wv + wD, bv + l * DMODEL, v, MROWS, DMODEL, DMODEL);

        attn_kernel<<<(BATCH * NHEAD * SEQ) / 8, 256>>>(q, k, v, att, a);
        global_attn_kernel<<<BATCH * NHEAD, 256>>>(q, k, v, att, a);

        gemm_kernel<0><<<gD, 256>>>(a, Wo + wD, bo + l * DMODEL, q, MROWS, DMODEL, DMODEL);
        addln_kernel<<<MROWS, 256>>>(x, q, ln1g + l * DMODEL, ln1b + l * DMODEL);

        gemm_kernel<1><<<gF, 256>>>(x, Wf1 + (size_t)l * DMODEL * DFF, bf1 + l * DFF, ff,
                                    MROWS, DFF, DMODEL);
        gemm_kernel<0><<<gD, 256>>>(ff, Wf2 + (size_t)l * DFF * DMODEL, bf2 + l * DMODEL, q,
                                    MROWS, DMODEL, DFF);
        addln_kernel<<<MROWS, 256>>>(x, q, ln2g + l * DMODEL, ln2b + l * DMODEL);
    }

    head_kernel<<<BATCH, 256>>>(x, att, Wh1, bh1, Wh2, bh2, (float*)d_out);
}

// round 14
// speedup vs baseline: 1.8104x; 1.8104x over previous
#include <cuda_runtime.h>
#include <cuda_bf16.h>
#include <math.h>

// Problem constants
#define BATCH 2
#define SEQ   4096
#define DMODEL 768
#define NHEAD 12
#define DHEAD 64
#define NLAYER 2
#define WIN   256
#define DFF   3072
#define MROWS (BATCH * SEQ)   // 8192

#define QT 64                  // queries per attention block
#define KT 32                  // keys per tile
#define NTILE ((2 * WIN + QT) / KT)   // 18
#define PCHUNK 64              // tokens per pooling chunk
#define NPC (SEQ / PCHUNK)     // 64 chunks per batch

// ---------------- scratch (static device allocations; no cudaMalloc) ----------------
__device__ float g_x [MROWS * DMODEL];
__device__ float g_q [MROWS * DMODEL];
__device__ float g_k [MROWS * DMODEL];
__device__ float g_v [MROWS * DMODEL];
__device__ float g_a [MROWS * DMODEL];
__device__ float g_ff[MROWS * DFF];
__device__ float g_pool[BATCH * NPC * DMODEL];   // pooling partials

// ---------------- helpers ----------------
__device__ __forceinline__ float gelu_tanh(float x) {
    float c = x + 0.044715f * x * x * x;
    return 0.5f * x * (1.0f + tanhf(0.7978845608028654f * c));
}

__device__ __forceinline__ unsigned f2tf32(float x) {
    unsigned r;
    asm("cvt.rna.tf32.f32 %0, %1;" : "=r"(r) : "f"(x));
    return r;
}

// block-wide sum of two values (blockDim.x == 256)
__device__ __forceinline__ void block_sum2(float& s1, float& s2) {
    #pragma unroll
    for (int o = 16; o; o >>= 1) {
        s1 += __shfl_xor_sync(0xffffffffu, s1, o);
        s2 += __shfl_xor_sync(0xffffffffu, s2, o);
    }
    __shared__ float sh1[8], sh2[8];
    int lane = threadIdx.x & 31, w = threadIdx.x >> 5;
    if (lane == 0) { sh1[w] = s1; sh2[w] = s2; }
    __syncthreads();
    float t1 = 0.f, t2 = 0.f;
    #pragma unroll
    for (int i = 0; i < 8; i++) { t1 += sh1[i]; t2 += sh2[i]; }
    s1 = t1; s2 = t2;
}

// ---------------- embedding + layernorm ----------------
__global__ void embed_ln_kernel(const int* __restrict__ ids,
                                const float* __restrict__ wemb,
                                const float* __restrict__ pemb,
                                const float* __restrict__ g,
                                const float* __restrict__ bt,
                                float* __restrict__ x) {
    int token = blockIdx.x;            // b*SEQ + s
    int s = token % SEQ;
    int id = ids[token];
    const float* wp = wemb + (size_t)id * DMODEL;
    const float* pp = pemb + (size_t)s * DMODEL;
    float* xp = x + (size_t)token * DMODEL;

    float v[3], s1 = 0.f, s2 = 0.f;
    #pragma unroll
    for (int j = 0; j < 3; j++) {
        int d = threadIdx.x + 256 * j;
        float val = wp[d] + pp[d];
        v[j] = val; s1 += val; s2 += val * val;
    }
    block_sum2(s1, s2);
    float mean = s1 * (1.0f / DMODEL);
    float var  = s2 * (1.0f / DMODEL) - mean * mean;
    float rstd = rsqrtf(var + 1e-5f);
    #pragma unroll
    for (int j = 0; j < 3; j++) {
        int d = threadIdx.x + 256 * j;
        xp[d] = (v[j] - mean) * rstd * g[d] + bt[d];
    }
}

// ---------------- x = LN(x + r) * g + b  (in place) ----------------
__global__ void addln_kernel(float* __restrict__ x,
                             const float* __restrict__ r,
                             const float* __restrict__ g,
                             const float* __restrict__ bt) {
    int token = blockIdx.x;
    float* xp = x + (size_t)token * DMODEL;
    const float* rp = r + (size_t)token * DMODEL;

    float v[3], s1 = 0.f, s2 = 0.f;
    #pragma unroll
    for (int j = 0; j < 3; j++) {
        int d = threadIdx.x + 256 * j;
        float val = xp[d] + rp[d];
        v[j] = val; s1 += val; s2 += val * val;
    }
    block_sum2(s1, s2);
    float mean = s1 * (1.0f / DMODEL);
    float var  = s2 * (1.0f / DMODEL) - mean * mean;
    float rstd = rsqrtf(var + 1e-5f);
    #pragma unroll
    for (int j = 0; j < 3; j++) {
        int d = threadIdx.x + 256 * j;
        xp[d] = (v[j] - mean) * rstd * g[d] + bt[d];
    }
}

// ---------------- tf32 tensor-core GEMM: C[M,N] = act(A[M,K] @ W[K,N] + bias) ----------------
// (unchanged from the passing round-5 kernel: 78.8 TF/s measured)
template <int ACT>
__global__ void __launch_bounds__(256)
gemm_kernel(const float* __restrict__ A, const float* __restrict__ W,
            const float* __restrict__ bias, float* __restrict__ C,
            int M, int N, int K) {
    __shared__ unsigned As[32][136];   // [k][m] tf32 bits
    __shared__ unsigned Bs[32][136];   // [k][n] tf32 bits

    const int tid = threadIdx.x;
    const int lane = tid & 31;
    const int wid = tid >> 5;
    const int gid = lane >> 2;
    const int tg  = lane & 3;
    const int warp_m = wid & 3;
    const int warp_n = wid >> 2;
    const int n0 = blockIdx.x * 128;
    const int m0 = blockIdx.y * 128;

    const int a_row = tid >> 1;
    const int a_kc  = (tid & 1) * 16;
    const int b_kr  = tid >> 3;
    const int b_nc  = (tid & 7) * 16;

    const float* Ag = A + (size_t)(m0 + a_row) * K + a_kc;
    const float* Wg = W + (size_t)b_kr * N + n0 + b_nc;

    float4 a_reg[4], b_reg[4];

    float acc[2][8][4];
    #pragma unroll
    for (int i = 0; i < 2; i++)
        #pragma unroll
        for (int j = 0; j < 8; j++)
            #pragma unroll
            for (int e = 0; e < 4; e++) acc[i][j][e] = 0.f;

    #pragma unroll
    for (int j = 0; j < 4; j++) {
        a_reg[j] = *(const float4*)(Ag + 4 * j);
        b_reg[j] = *(const float4*)(Wg + 4 * j);
    }
    #pragma unroll
    for (int j = 0; j < 4; j++) {
        As[a_kc + 4 * j + 0][a_row] = f2tf32(a_reg[j].x);
        As[a_kc + 4 * j + 1][a_row] = f2tf32(a_reg[j].y);
        As[a_kc + 4 * j + 2][a_row] = f2tf32(a_reg[j].z);
        As[a_kc + 4 * j + 3][a_row] = f2tf32(a_reg[j].w);
        uint4 u;
        u.x = f2tf32(b_reg[j].x); u.y = f2tf32(b_reg[j].y);
        u.z = f2tf32(b_reg[j].z); u.w = f2tf32(b_reg[j].w);
        *(uint4*)(&Bs[b_kr][b_nc + 4 * j]) = u;
    }
    __syncthreads();

    for (int kt = 0; kt < K; kt += 32) {
        const bool has_next = (kt + 32) < K;
        if (has_next) {
            #pragma unroll
            for (int j = 0; j < 4; j++) {
                a_reg[j] = *(const float4*)(Ag + kt + 32 + 4 * j);
                b_reg[j] = *(const float4*)(Wg + (size_t)(kt + 32) * N + 4 * j);
            }
        }

        #pragma unroll
        for (int kk = 0; kk < 4; kk++) {
            const int k8 = kk * 8;
            unsigned af[2][4], bf[8][2];
            #pragma unroll
            for (int fm = 0; fm < 2; fm++) {
                int mb = warp_m * 32 + fm * 16;
                af[fm][0] = As[k8 + tg    ][mb + gid];
                af[fm][1] = As[k8 + tg    ][mb + gid + 8];
                af[fm][2] = As[k8 + tg + 4][mb + gid];
                af[fm][3] = As[k8 + tg + 4][mb + gid + 8];
            }
            #pragma unroll
            for (int fn = 0; fn < 8; fn++) {
                int nb = warp_n * 64 + fn * 8;
                bf[fn][0] = Bs[k8 + tg    ][nb + gid];
                bf[fn][1] = Bs[k8 + tg + 4][nb + gid];
            }
            #pragma unroll
            for (int fm = 0; fm < 2; fm++)
                #pragma unroll
                for (int fn = 0; fn < 8; fn++) {
                    asm volatile(
                        "mma.sync.aligned.m16n8k8.row.col.f32.tf32.tf32.f32 "
                        "{%0,%1,%2,%3}, {%4,%5,%6,%7}, {%8,%9}, {%0,%1,%2,%3};"
                        : "+f"(acc[fm][fn][0]), "+f"(acc[fm][fn][1]),
                          "+f"(acc[fm][fn][2]), "+f"(acc[fm][fn][3])
                        : "r"(af[fm][0]), "r"(af[fm][1]), "r"(af[fm][2]), "r"(af[fm][3]),
                          "r"(bf[fn][0]), "r"(bf[fn][1]));
                }
        }

        if (has_next) {
            __syncthreads();
            #pragma unroll
            for (int j = 0; j < 4; j++) {
                As[a_kc + 4 * j + 0][a_row] = f2tf32(a_reg[j].x);
                As[a_kc + 4 * j + 1][a_row] = f2tf32(a_reg[j].y);
                As[a_kc + 4 * j + 2][a_row] = f2tf32(a_reg[j].z);
                As[a_kc + 4 * j + 3][a_row] = f2tf32(a_reg[j].w);
                uint4 u;
                u.x = f2tf32(b_reg[j].x); u.y = f2tf32(b_reg[j].y);
                u.z = f2tf32(b_reg[j].z); u.w = f2tf32(b_reg[j].w);
                *(uint4*)(&Bs[b_kr][b_nc + 4 * j]) = u;
            }
            __syncthreads();
        }
    }

    #pragma unroll
    for (int fn = 0; fn < 8; fn++) {
        int nb = n0 + warp_n * 64 + fn * 8 + 2 * tg;
        float b0 = bias[nb], b1 = bias[nb + 1];
        #pragma unroll
        for (int fm = 0; fm < 2; fm++) {
            int mb = m0 + warp_m * 32 + fm * 16;
            float v0 = acc[fm][fn][0] + b0;
            float v1 = acc[fm][fn][1] + b1;
            float v2 = acc[fm][fn][2] + b0;
            float v3 = acc[fm][fn][3] + b1;
            if (ACT == 1) {
                v0 = gelu_tanh(v0); v1 = gelu_tanh(v1);
                v2 = gelu_tanh(v2); v3 = gelu_tanh(v3);
            }
            *(float2*)(C + (size_t)(mb + gid)     * N + nb) = make_float2(v0, v1);
            *(float2*)(C + (size_t)(mb + gid + 8) * N + nb) = make_float2(v2, v3);
        }
    }
}

// ---------------- block-tiled sliding-window + global attention ----------------
// Block = (b, h, 64 queries). Keys processed in tiles of 32 from the shared
// band [t0-256, t0+319]. Two smem micro-GEMMs (QK^T and PV) with one 4-level
// shfl max/sum per tile per query row (amortized over 32 keys). Global key 0
// initializes the online-softmax state. Query t==0 is recomputed (overwritten)
// by global_attn_kernel afterwards.
__global__ void __launch_bounds__(256)
attn_tiled_kernel(const float* __restrict__ q,
                  const float* __restrict__ k,
                  const float* __restrict__ v,
                  const int* __restrict__ att,
                  float* __restrict__ out) {
    __shared__ float QsT[64][68];     // [d][q], pre-scaled
    __shared__ float KsT[64][36];     // [d][k]
    __shared__ float Vs [KT][68];     // [k][d]
    __shared__ float Ps [KT][68];     // [k][q]
    __shared__ float K0s[64], V0s[64];
    __shared__ float amask[KT];

    const int tid = threadIdx.x;
    const int nchunk = SEQ / QT;                      // 64
    const int chunk = blockIdx.x % nchunk;
    const int h = (blockIdx.x / nchunk) % NHEAD;
    const int b = blockIdx.x / (nchunk * NHEAD);
    const int t0 = chunk * QT;

    const int qg = tid >> 4;      // 0..15 (4 queries each)
    const int kg = tid & 15;      // score role: 2 keys; PV role: 4 dims

    const float* qbase = q + (size_t)(b * SEQ + t0) * DMODEL + h * DHEAD;
    const float* kb = k + (size_t)b * SEQ * DMODEL + h * DHEAD;
    const float* vb = v + (size_t)b * SEQ * DMODEL + h * DHEAD;
    const int* ab = att + b * SEQ;

    // load Q tile transposed + scaled
    {
        int qloc = tid >> 2;                 // 0..63
        int d0 = (tid & 3) * 16;
        const float* qp = qbase + (size_t)qloc * DMODEL + d0;
        #pragma unroll
        for (int j = 0; j < 4; j++) {
            float4 qv = *(const float4*)(qp + 4 * j);
            QsT[d0 + 4 * j + 0][qloc] = qv.x * 0.125f;
            QsT[d0 + 4 * j + 1][qloc] = qv.y * 0.125f;
            QsT[d0 + 4 * j + 2][qloc] = qv.z * 0.125f;
            QsT[d0 + 4 * j + 3][qloc] = qv.w * 0.125f;
        }
    }
    if (tid < 64) { K0s[tid] = kb[tid]; V0s[tid] = vb[tid]; }
    __syncthreads();

    // global-key init: m = q.k0, l = 1, acc = v0
    float m[4], l[4], acc[4][4];
    {
        float sg[4] = {0.f, 0.f, 0.f, 0.f};
        for (int d = 0; d < 64; d++) {
            float kk = K0s[d];
            float4 qv = *(const float4*)&QsT[d][qg * 4];
            sg[0] += qv.x * kk; sg[1] += qv.y * kk;
            sg[2] += qv.z * kk; sg[3] += qv.w * kk;
        }
        #pragma unroll
        for (int i = 0; i < 4; i++) { m[i] = sg[i]; l[i] = 1.f; }
        #pragma unroll
        for (int j = 0; j < 4; j++) {
            float vv = V0s[kg * 4 + j];
            #pragma unroll
            for (int i = 0; i < 4; i++) acc[i][j] = vv;
        }
    }

    for (int it = 0; it < NTILE; it++) {
        int kt0 = t0 - WIN + it * KT;
        if (kt0 + KT - 1 < 1 || kt0 >= SEQ) continue;   // uniform per block

        __syncthreads();   // previous tile's readers of Vs/Ps/KsT are done

        // load K tile (transposed) + V tile + key mask
        {
            int kloc = tid >> 3;               // 0..31
            int d0 = (tid & 7) * 8;
            int key = kt0 + kloc;
            int keyc = min(max(key, 0), SEQ - 1);
            const float* kp = kb + (size_t)keyc * DMODEL + d0;
            const float* vp = vb + (size_t)keyc * DMODEL + d0;
            #pragma unroll
            for (int j = 0; j < 2; j++) {
                float4 kk4 = *(const float4*)(kp + 4 * j);
                KsT[d0 + 4 * j + 0][kloc] = kk4.x;
                KsT[d0 + 4 * j + 1][kloc] = kk4.y;
                KsT[d0 + 4 * j + 2][kloc] = kk4.z;
                KsT[d0 + 4 * j + 3][kloc] = kk4.w;
                *(float4*)&Vs[kloc][d0 + 4 * j] = *(const float4*)(vp + 4 * j);
            }
        }
        if (tid < KT) {
            int key = kt0 + tid;
            bool ok = (key >= 1) && (key < SEQ);
            if (ok) ok = ab[key] > 0;
            amask[tid] = ok ? 0.f : -1e30f;
        }
        __syncthreads();

        // scores: s[4q][2k]
        float s[4][2];
        #pragma unroll
        for (int i = 0; i < 4; i++) { s[i][0] = 0.f; s[i][1] = 0.f; }
        for (int d = 0; d < 64; d++) {
            float4 qv = *(const float4*)&QsT[d][qg * 4];
            float2 kv = *(const float2*)&KsT[d][kg * 2];
            s[0][0] += qv.x * kv.x; s[0][1] += qv.x * kv.y;
            s[1][0] += qv.y * kv.x; s[1][1] += qv.y * kv.y;
            s[2][0] += qv.z * kv.x; s[2][1] += qv.z * kv.y;
            s[3][0] += qv.w * kv.x; s[3][1] += qv.w * kv.y;
        }
        float am0 = amask[kg * 2], am1 = amask[kg * 2 + 1];
        int base = kt0 - t0 + kg * 2;       // (key@j=0) - t0
        #pragma unroll
        for (int i = 0; i < 4; i++) {
            int dlt = base - (qg * 4 + i);  // key - query, j=0
            s[i][0] += am0 + (((unsigned)(dlt + WIN)     <= 2u * WIN) ? 0.f : -1e30f);
            s[i][1] += am1 + (((unsigned)(dlt + 1 + WIN) <= 2u * WIN) ? 0.f : -1e30f);
        }

        // online softmax per query row (reduce across kg = 16 threads)
        float corr[4];
        #pragma unroll
        for (int i = 0; i < 4; i++) {
            float tm = fmaxf(s[i][0], s[i][1]);
            #pragma unroll
            for (int o = 1; o < 16; o <<= 1)
                tm = fmaxf(tm, __shfl_xor_sync(0xffffffffu, tm, o));
            float mn = fmaxf(m[i], tm);
            float p0 = __expf(s[i][0] - mn);
            float p1 = __expf(s[i][1] - mn);
            float ts = p0 + p1;
            #pragma unroll
            for (int o = 1; o < 16; o <<= 1)
                ts += __shfl_xor_sync(0xffffffffu, ts, o);
            corr[i] = __expf(m[i] - mn);
            l[i] = l[i] * corr[i] + ts;
            m[i] = mn;
            Ps[kg * 2    ][qg * 4 + i] = p0;
            Ps[kg * 2 + 1][qg * 4 + i] = p1;
        }
        __syncthreads();   // Ps visible; score phase done reading KsT

        // PV: acc[4q][4d] += P(64q x 32k) @ V(32k x 64d), d = kg*4..+3
        #pragma unroll
        for (int i = 0; i < 4; i++)
            #pragma unroll
            for (int j = 0; j < 4; j++) acc[i][j] *= corr[i];
        for (int kk2 = 0; kk2 < KT; kk2++) {
            float4 pv = *(const float4*)&Ps[kk2][qg * 4];
            float4 vv = *(const float4*)&Vs[kk2][kg * 4];
            acc[0][0] += pv.x * vv.x; acc[0][1] += pv.x * vv.y;
            acc[0][2] += pv.x * vv.z; acc[0][3] += pv.x * vv.w;
            acc[1][0] += pv.y * vv.x; acc[1][1] += pv.y * vv.y;
            acc[1][2] += pv.y * vv.z; acc[1][3] += pv.y * vv.w;
            acc[2][0] += pv.z * vv.x; acc[2][1] += pv.z * vv.y;
            acc[2][2] += pv.z * vv.z; acc[2][3] += pv.z * vv.w;
            acc[3][0] += pv.w * vv.x; acc[3][1] += pv.w * vv.y;
            acc[3][2] += pv.w * vv.z; acc[3][3] += pv.w * vv.w;
        }
    }

    // write: out[q][d], q = t0 + qg*4+i, d = kg*4..+3
    #pragma unroll
    for (int i = 0; i < 4; i++) {
        float inv = 1.0f / l[i];
        float4 o4 = make_float4(acc[i][0] * inv, acc[i][1] * inv,
                                acc[i][2] * inv, acc[i][3] * inv);
        *(float4*)(out + (size_t)(b * SEQ + t0 + qg * 4 + i) * DMODEL
                       + h * DHEAD + kg * 4) = o4;
    }
}

// ---------------- global query (t == 0): full attention over all masked keys ----------------
__global__ void global_attn_kernel(const float* __restrict__ q,
                                   const float* __restrict__ k,
                                   const float* __restrict__ v,
                                   const int* __restrict__ att,
                                   float* __restrict__ out) {
    int h = blockIdx.x % NHEAD;
    int b = blockIdx.x / NHEAD;
    int lane = threadIdx.x & 31;
    int w = threadIdx.x >> 5;

    const float scale = 0.125f;
    const float2* qp = (const float2*)(q + (size_t)(b * SEQ) * DMODEL + h * DHEAD);
    float2 qv = qp[lane];
    float q0 = qv.x * scale, q1 = qv.y * scale;

    const float* kb = k + (size_t)b * SEQ * DMODEL + h * DHEAD;
    const float* vb = v + (size_t)b * SEQ * DMODEL + h * DHEAD;
    const int* ab = att + b * SEQ;

    float m = -1e30f, l = 0.f, a0 = 0.f, a1 = 0.f;

    for (int s = w; s < SEQ; s += 8) {
        float2 kk = ((const float2*)(kb + (size_t)s * DMODEL))[lane];
        float part = q0 * kk.x + q1 * kk.y;
        #pragma unroll
        for (int o = 16; o; o >>= 1) part += __shfl_xor_sync(0xffffffffu, part, o);
        float sc = part + (ab[s] > 0 ? 0.f : -1e30f);
        float mn = fmaxf(m, sc);
        float corr = __expf(m - mn);
        float p = __expf(sc - mn);
        float2 vv = ((const float2*)(vb + (size_t)s * DMODEL))[lane];
        a0 = a0 * corr + p * vv.x;
        a1 = a1 * corr + p * vv.y;
        l = l * corr + p;
        m = mn;
    }

    __shared__ float sm[8], sl[8];
    __shared__ float sacc[8][64];
    if (lane == 0) { sm[w] = m; sl[w] = l; }
    sacc[w][2 * lane]     = a0;
    sacc[w][2 * lane + 1] = a1;
    __syncthreads();

    if (w == 0) {
        float M = -1e30f;
        #pragma unroll
        for (int i = 0; i < 8; i++) M = fmaxf(M, sm[i]);
        float L = 0.f, o0 = 0.f, o1 = 0.f;
        #pragma unroll
        for (int i = 0; i < 8; i++) {
            float c = __expf(sm[i] - M);
            L  += sl[i] * c;
            o0 += sacc[i][2 * lane]     * c;
            o1 += sacc[i][2 * lane + 1] * c;
        }
        float inv = 1.0f / L;
        float2* op = (float2*)(out + (size_t)(b * SEQ) * DMODEL + h * DHEAD);
        op[lane] = make_float2(o0 * inv, o1 * inv);
    }
}

// ---------------- pooling stage 1: per-chunk masked partial sums ----------------
// Block = (b, chunk of 64 tokens). 256 threads; thread d-strided over DMODEL.
__global__ void pool_partial_kernel(const float* __restrict__ x,
                                    const int* __restrict__ att,
                                    float* __restrict__ pool) {
    int chunk = blockIdx.x % NPC;
    int b = blockIdx.x / NPC;
    int tid = threadIdx.x;
    int s0 = chunk * PCHUNK;

    const float* xp = x + (size_t)(b * SEQ + s0) * DMODEL;
    const int* ap = att + b * SEQ + s0;
    float* pp = pool + (size_t)(b * NPC + chunk) * DMODEL;

    float acc[3] = {0.f, 0.f, 0.f};
    for (int s = 0; s < PCHUNK; s++) {
        float msk = (float)ap[s];
        const float* row = xp + (size_t)s * DMODEL;
        #pragma unroll
        for (int j = 0; j < 3; j++)
            acc[j] += row[tid + 256 * j] * msk;
    }
    #pragma unroll
    for (int j = 0; j < 3; j++)
        pp[tid + 256 * j] = acc[j];
}

// ---------------- pooled head: reduce partials -> relu MLP -> sigmoid*4 ----------------
__global__ void head_kernel(const float* __restrict__ pool,
                            const int* __restrict__ att,
                            const float* __restrict__ Wh1, const float* __restrict__ bh1,
                            const float* __restrict__ Wh2, const float* __restrict__ bh2,
                            float* __restrict__ out) {
    int b = blockIdx.x;
    int tid = threadIdx.x;
    __shared__ float pooled[DMODEL];
    __shared__ float h[256];

    float cnt = 0.f, dummy = 0.f;
    for (int s = tid; s < SEQ; s += 256) cnt += (float)att[b * SEQ + s];
    block_sum2(cnt, dummy);
    float denom = fmaxf(cnt, 1e-9f);

    // reduce 64 chunk partials in fixed order (deterministic)
    #pragma unroll
    for (int j = 0; j < 3; j++) {
        int d = tid + 256 * j;
        float ssum = 0.f;
        const float* pp = pool + (size_t)b * NPC * DMODEL + d;
        for (int c = 0; c < NPC; c++)
            ssum += pp[(size_t)c * DMODEL];
        pooled[d] = ssum / denom;
    }
    __syncthreads();

    {
        float acc = bh1[tid];
        for (int kk = 0; kk < DMODEL; kk++)
            acc += pooled[kk] * Wh1[kk * 256 + tid];
        h[tid] = fmaxf(acc, 0.f);
    }
    __syncthreads();

    if (tid < 14) {
        float acc = bh2[tid];
        for (int kk = 0; kk < 256; kk++)
            acc += h[kk] * Wh2[kk * 14 + tid];
        out[b * 14 + tid] = 4.0f / (1.0f + expf(-acc));
    }
}

// ---------------- launch ----------------
extern "C" void kernel_launch(void* const* d_in, const int* in_sizes, int n_in,
                              void* d_out, int out_size) {
    const int*   ids  = (const int*)  d_in[0];
    const int*   att  = (const int*)  d_in[1];
    const float* wemb = (const float*)d_in[2];
    const float* pemb = (const float*)d_in[3];
    const float* eg   = (const float*)d_in[4];
    const float* eb   = (const float*)d_in[5];
    const float* Wq   = (const float*)d_in[6];
    const float* bq   = (const float*)d_in[7];
    const float* Wk   = (const float*)d_in[8];
    const float* bk   = (const float*)d_in[9];
    const float* Wv   = (const float*)d_in[10];
    const float* bv   = (const float*)d_in[11];
    const float* Wo   = (const float*)d_in[12];
    const float* bo   = (const float*)d_in[13];
    const float* ln1g = (const float*)d_in[14];
    const float* ln1b = (const float*)d_in[15];
    const float* Wf1  = (const float*)d_in[16];
    const float* bf1  = (const float*)d_in[17];
    const float* Wf2  = (const float*)d_in[18];
    const float* bf2  = (const float*)d_in[19];
    const float* ln2g = (const float*)d_in[20];
    const float* ln2b = (const float*)d_in[21];
    const float* Wh1  = (const float*)d_in[22];
    const float* bh1  = (const float*)d_in[23];
    const float* Wh2  = (const float*)d_in[24];
    const float* bh2  = (const float*)d_in[25];

    float *x, *q, *k, *v, *a, *ff, *pool;
    cudaGetSymbolAddress((void**)&x,    g_x);
    cudaGetSymbolAddress((void**)&q,    g_q);
    cudaGetSymbolAddress((void**)&k,    g_k);
    cudaGetSymbolAddress((void**)&v,    g_v);
    cudaGetSymbolAddress((void**)&a,    g_a);
    cudaGetSymbolAddress((void**)&ff,   g_ff);
    cudaGetSymbolAddress((void**)&pool, g_pool);

    dim3 gD(DMODEL / 128, MROWS / 128);   // (6, 64)
    dim3 gF(DFF / 128,    MROWS / 128);   // (24, 64)

    embed_ln_kernel<<<MROWS, 256>>>(ids, wemb, pemb, eg, eb, x);

    for (int l = 0; l < NLAYER; l++) {
        const size_t wD = (size_t)l * DMODEL * DMODEL;
        gemm_kernel<0><<<gD, 256>>>(x, Wq + wD, bq + l * DMODEL, q, MROWS, DMODEL, DMODEL);
        gemm_kernel<0><<<gD, 256>>>(x, Wk + wD, bk + l * DMODEL, k, MROWS, DMODEL, DMODEL);
        gemm_kernel<0><<<gD, 256>>>(x, Wv + wD, bv + l * DMODEL, v, MROWS, DMODEL, DMODEL);

        attn_tiled_kernel<<<BATCH * NHEAD * (SEQ / QT), 256>>>(q, k, v, att, a);
        global_attn_kernel<<<BATCH * NHEAD, 256>>>(q, k, v, att, a);

        gemm_kernel<0><<<gD, 256>>>(a, Wo + wD, bo + l * DMODEL, q, MROWS, DMODEL, DMODEL);
        addln_kernel<<<MROWS, 256>>>(x, q, ln1g + l * DMODEL, ln1b + l * DMODEL);

        gemm_kernel<1><<<gF, 256>>>(x, Wf1 + (size_t)l * DMODEL * DFF, bf1 + l * DFF, ff,
                                    MROWS, DFF, DMODEL);
        gemm_kernel<0><<<gD, 256>>>(ff, Wf2 + (size_t)l * DFF * DMODEL, bf2 + l * DMODEL, q,
                                    MROWS, DMODEL, DFF);
        addln_kernel<<<MROWS, 256>>>(x, q, ln2g + l * DMODEL, ln2b + l * DMODEL);
    }

    pool_partial_kernel<<<BATCH * NPC, 256>>>(x, att, pool);
    head_kernel<<<BATCH, 256>>>(pool, att, Wh1, bh1, Wh2, bh2, (float*)d_out);
}